// round 1
// baseline (speedup 1.0000x reference)
#include <cuda_runtime.h>
#include <math.h>

// ---------------------------------------------------------------------------
// GIN (3 GINConv layers + BN + ReLU + MLP head) for:
//   N_NODES=100000, N_EDGES=1200000, D_IN=128, D_H=64, N_GRAPHS=256
// Strategy:
//   per layer: agg = copy(h_prev); red.v4 scatter-add over edges;
//              fused [GEMM1 -> BN(folded) -> ReLU -> GEMM2 -> ReLU -> pool-red]
//   final: pooled [256,192] -> relu(lin1) -> lin2 -> log_softmax
// ---------------------------------------------------------------------------

#define MAX_NODES 100000
#define NGRAPH    256

__device__ float g_agg[MAX_NODES * 128];      // aggregation buffer (reused, 64-d layers use prefix)
__device__ float g_h1 [MAX_NODES * 64];
__device__ float g_h2 [MAX_NODES * 64];
__device__ float g_h3 [MAX_NODES * 64];
__device__ float g_pool[NGRAPH * 192];

// ---------------------------------------------------------------------------
__global__ void zero_kernel(float* __restrict__ p, int n) {
    int i = blockIdx.x * blockDim.x + threadIdx.x;
    if (i < n) p[i] = 0.f;
}

__global__ void copy4_kernel(float4* __restrict__ dst, const float4* __restrict__ src, int n4) {
    int i = blockIdx.x * blockDim.x + threadIdx.x;
    if (i < n4) dst[i] = src[i];
}

// ---------------------------------------------------------------------------
// Edge scatter: agg[dst] += h[src].  D4 = float4's per row (32 for D=128, 16 for D=64).
// One edge handled by D4 consecutive threads; vector reduction (no return).
// ---------------------------------------------------------------------------
template<int D4>
__global__ void scatter_kernel(const float* __restrict__ h,
                               const int*   __restrict__ ei,   // [2, n_edges]
                               float*       __restrict__ agg,
                               int n_edges) {
    int t    = blockIdx.x * blockDim.x + threadIdx.x;
    int e    = t / D4;
    int lane = t - e * D4;
    if (e >= n_edges) return;
    int s = __ldg(ei + e);
    int d = __ldg(ei + n_edges + e);
    float4 v = __ldg((const float4*)h + (size_t)s * D4 + lane);
    float4* ad = (float4*)agg + (size_t)d * D4 + lane;
    asm volatile("red.global.add.v4.f32 [%0], {%1,%2,%3,%4};"
                 :: "l"(ad), "f"(v.x), "f"(v.y), "f"(v.z), "f"(v.w) : "memory");
}

// ---------------------------------------------------------------------------
// Fused per-layer MLP:
//   h = relu( relu( BN( agg @ w1 + b1 ) ) @ w2 + b2 )   (BN folded to scale/shift)
//   hout[node] = h ; pool[batch[node], pool_off:pool_off+64] += h
// One thread per node; 64 fp32 accumulators; weights broadcast from smem.
// smem sA (32KB) holds w1 during GEMM1, then is recycled as the per-thread
// column-major intermediate (hm[j*128+tid]) — conflict-free, self-column only.
// ---------------------------------------------------------------------------
template<int DIN>
__global__ __launch_bounds__(128) void mlp_kernel(
    const float* __restrict__ agg,
    const float* __restrict__ w1, const float* __restrict__ b1,
    const float* __restrict__ gg, const float* __restrict__ bt,
    const float* __restrict__ rm, const float* __restrict__ rv,
    const float* __restrict__ w2, const float* __restrict__ b2,
    float*       __restrict__ hout,
    const int*   __restrict__ batch,
    float*       __restrict__ pool, int pool_off, int n_nodes)
{
    __shared__ float sA[128 * 64];   // w1 (DIN*64 floats) then hm (64 x 128)
    __shared__ float w2s[64 * 64];

    int tid = threadIdx.x;
    for (int i = tid; i < DIN * 64; i += 128) sA[i]  = w1[i];
    for (int i = tid; i < 64 * 64;  i += 128) w2s[i] = w2[i];
    __syncthreads();

    int  node   = blockIdx.x * 128 + tid;
    bool active = node < n_nodes;
    int  nodec  = active ? node : (n_nodes - 1);

    float acc[64];
#pragma unroll
    for (int j = 0; j < 64; j++) acc[j] = 0.f;

    // ---- GEMM1: acc = agg_row @ w1 ----
    const float4* arow = (const float4*)(agg + (size_t)nodec * DIN);
    for (int k4 = 0; k4 < DIN / 4; k4++) {
        float4 hv = __ldg(arow + k4);
        float hvv[4] = {hv.x, hv.y, hv.z, hv.w};
#pragma unroll
        for (int kk = 0; kk < 4; kk++) {
            float hk = hvv[kk];
            const float4* wrow = (const float4*)(sA + (k4 * 4 + kk) * 64);
#pragma unroll
            for (int j4 = 0; j4 < 16; j4++) {
                float4 wv = wrow[j4];
                acc[j4*4+0] = fmaf(hk, wv.x, acc[j4*4+0]);
                acc[j4*4+1] = fmaf(hk, wv.y, acc[j4*4+1]);
                acc[j4*4+2] = fmaf(hk, wv.z, acc[j4*4+2]);
                acc[j4*4+3] = fmaf(hk, wv.w, acc[j4*4+3]);
            }
        }
    }

    // ---- BN (eval, folded) + ReLU ----
#pragma unroll 8
    for (int j = 0; j < 64; j++) {
        float sc = __ldg(gg + j) * rsqrtf(__ldg(rv + j) + 1e-5f);
        float sh = (__ldg(b1 + j) - __ldg(rm + j)) * sc + __ldg(bt + j);
        acc[j] = fmaxf(fmaf(acc[j], sc, sh), 0.f);
    }

    __syncthreads();   // all threads finished reading w1 region
#pragma unroll
    for (int j = 0; j < 64; j++) sA[j * 128 + tid] = acc[j];
    // (no barrier needed: each thread reads back only its own column)

    // ---- GEMM2: acc = hm_row @ w2 ----
#pragma unroll
    for (int j = 0; j < 64; j++) acc[j] = 0.f;
#pragma unroll 4
    for (int k = 0; k < 64; k++) {
        float hk = sA[k * 128 + tid];
        const float4* wrow = (const float4*)(w2s + k * 64);
#pragma unroll
        for (int j4 = 0; j4 < 16; j4++) {
            float4 wv = wrow[j4];
            acc[j4*4+0] = fmaf(hk, wv.x, acc[j4*4+0]);
            acc[j4*4+1] = fmaf(hk, wv.y, acc[j4*4+1]);
            acc[j4*4+2] = fmaf(hk, wv.z, acc[j4*4+2]);
            acc[j4*4+3] = fmaf(hk, wv.w, acc[j4*4+3]);
        }
    }

    // ---- bias + ReLU + store + pooled reduction ----
    if (active) {
        float4* orow = (float4*)(hout + (size_t)node * 64);
        float*  prow = pool + (size_t)__ldg(batch + node) * 192 + pool_off;
#pragma unroll
        for (int j4 = 0; j4 < 16; j4++) {
            float4 v;
            v.x = fmaxf(acc[j4*4+0] + __ldg(b2 + j4*4+0), 0.f);
            v.y = fmaxf(acc[j4*4+1] + __ldg(b2 + j4*4+1), 0.f);
            v.z = fmaxf(acc[j4*4+2] + __ldg(b2 + j4*4+2), 0.f);
            v.w = fmaxf(acc[j4*4+3] + __ldg(b2 + j4*4+3), 0.f);
            orow[j4] = v;
            asm volatile("red.global.add.v4.f32 [%0], {%1,%2,%3,%4};"
                         :: "l"(prow + j4 * 4),
                            "f"(v.x), "f"(v.y), "f"(v.z), "f"(v.w) : "memory");
        }
    }
}

// ---------------------------------------------------------------------------
// Final head: one block (64 threads) per graph.
//   hid = relu(pool_row @ lin1_w + lin1_b); z = hid @ lin2_w + lin2_b; log_softmax
// ---------------------------------------------------------------------------
__global__ void final_kernel(const float* __restrict__ pool,
                             const float* __restrict__ lw1, const float* __restrict__ lb1,
                             const float* __restrict__ lw2, const float* __restrict__ lb2,
                             float* __restrict__ out)
{
    __shared__ float prow[192];
    __shared__ float hid[64];
    __shared__ float zz[2];
    int g = blockIdx.x, j = threadIdx.x;
    for (int k = j; k < 192; k += 64) prow[k] = pool[g * 192 + k];
    __syncthreads();
    float a = __ldg(lb1 + j);
    for (int k = 0; k < 192; k++) a = fmaf(prow[k], __ldg(lw1 + k * 64 + j), a);
    hid[j] = fmaxf(a, 0.f);
    __syncthreads();
    if (j < 2) {
        float z = __ldg(lb2 + j);
#pragma unroll 8
        for (int k = 0; k < 64; k++) z = fmaf(hid[k], __ldg(lw2 + k * 2 + j), z);
        zz[j] = z;
    }
    __syncthreads();
    if (j == 0) {
        float m   = fmaxf(zz[0], zz[1]);
        float lse = m + logf(expf(zz[0] - m) + expf(zz[1] - m));
        out[g * 2 + 0] = zz[0] - lse;
        out[g * 2 + 1] = zz[1] - lse;
    }
}

// ---------------------------------------------------------------------------
extern "C" void kernel_launch(void* const* d_in, const int* in_sizes, int n_in,
                              void* d_out, int out_size)
{
    const float* x     = (const float*)d_in[0];
    const int*   ei    = (const int*)  d_in[1];
    const int*   batch = (const int*)  d_in[2];

    // num_graphs may or may not materialize as a device input; detect by size.
    int wi = (in_sizes[3] < 64) ? 4 : 3;
    const float* W[28];
    for (int i = 0; i < 28 && wi + i < n_in; i++) W[i] = (const float*)d_in[wi + i];

    int n_nodes = in_sizes[0] / 128;
    int n_edges = in_sizes[1] / 2;

    float *agg, *h1, *h2, *h3, *pool;
    cudaGetSymbolAddress((void**)&agg,  g_agg);
    cudaGetSymbolAddress((void**)&h1,   g_h1);
    cudaGetSymbolAddress((void**)&h2,   g_h2);
    cudaGetSymbolAddress((void**)&h3,   g_h3);
    cudaGetSymbolAddress((void**)&pool, g_pool);

    float* out = (float*)d_out;

    zero_kernel<<<(NGRAPH * 192 + 255) / 256, 256>>>(pool, NGRAPH * 192);

    // ---- layer 1 (DIN = 128) ----
    {
        int n4 = n_nodes * 128 / 4;
        copy4_kernel<<<(n4 + 255) / 256, 256>>>((float4*)agg, (const float4*)x, n4);
        long long tt = (long long)n_edges * 32;
        scatter_kernel<32><<<(int)((tt + 255) / 256), 256>>>(x, ei, agg, n_edges);
        mlp_kernel<128><<<(n_nodes + 127) / 128, 128>>>(
            agg, W[0], W[1], W[2], W[3], W[4], W[5], W[6], W[7],
            h1, batch, pool, 0, n_nodes);
    }
    // ---- layer 2 (DIN = 64) ----
    {
        int n4 = n_nodes * 64 / 4;
        copy4_kernel<<<(n4 + 255) / 256, 256>>>((float4*)agg, (const float4*)h1, n4);
        long long tt = (long long)n_edges * 16;
        scatter_kernel<16><<<(int)((tt + 255) / 256), 256>>>(h1, ei, agg, n_edges);
        mlp_kernel<64><<<(n_nodes + 127) / 128, 128>>>(
            agg, W[8], W[9], W[10], W[11], W[12], W[13], W[14], W[15],
            h2, batch, pool, 64, n_nodes);
    }
    // ---- layer 3 (DIN = 64) ----
    {
        int n4 = n_nodes * 64 / 4;
        copy4_kernel<<<(n4 + 255) / 256, 256>>>((float4*)agg, (const float4*)h2, n4);
        long long tt = (long long)n_edges * 16;
        scatter_kernel<16><<<(int)((tt + 255) / 256), 256>>>(h2, ei, agg, n_edges);
        mlp_kernel<64><<<(n_nodes + 127) / 128, 128>>>(
            agg, W[16], W[17], W[18], W[19], W[20], W[21], W[22], W[23],
            h3, batch, pool, 128, n_nodes);
    }

    final_kernel<<<NGRAPH, 64>>>(pool, W[24], W[25], W[26], W[27], out);
}

// round 2
// speedup vs baseline: 1.3923x; 1.3923x over previous
#include <cuda_runtime.h>
#include <math.h>

// ---------------------------------------------------------------------------
// GIN (3 GINConv layers + BN + ReLU + MLP head)
//   N_NODES=100000, N_EDGES=1200000, D_IN=128, D_H=64, N_GRAPHS=256
// R1 changes vs R0:
//   * mlp kernel: packed fma.rn.f32x2 (halves FMA warp-instrs)
//   * GEMM2 reads intermediate h from registers (no smem round-trip)
//   * w1/w2 staged sequentially into ONE smem buffer (48KB -> 32/16KB)
// ---------------------------------------------------------------------------

#define MAX_NODES 100000
#define NGRAPH    256

__device__ float g_agg[MAX_NODES * 128];
__device__ float g_h1 [MAX_NODES * 64];
__device__ float g_h2 [MAX_NODES * 64];
__device__ float g_h3 [MAX_NODES * 64];
__device__ float g_pool[NGRAPH * 192];

typedef unsigned long long ull;

__device__ __forceinline__ ull pack2(float lo, float hi) {
    ull r; asm("mov.b64 %0,{%1,%2};" : "=l"(r) : "f"(lo), "f"(hi)); return r;
}
__device__ __forceinline__ void unpack2(ull v, float& lo, float& hi) {
    asm("mov.b64 {%0,%1},%2;" : "=f"(lo), "=f"(hi) : "l"(v));
}
__device__ __forceinline__ ull fma2(ull a, ull b, ull c) {
    ull d; asm("fma.rn.f32x2 %0,%1,%2,%3;" : "=l"(d) : "l"(a), "l"(b), "l"(c)); return d;
}

// ---------------------------------------------------------------------------
__global__ void zero_kernel(float* __restrict__ p, int n) {
    int i = blockIdx.x * blockDim.x + threadIdx.x;
    if (i < n) p[i] = 0.f;
}

__global__ void copy4_kernel(float4* __restrict__ dst, const float4* __restrict__ src, int n4) {
    int i = blockIdx.x * blockDim.x + threadIdx.x;
    if (i < n4) dst[i] = src[i];
}

// ---------------------------------------------------------------------------
// Edge scatter: agg[dst] += h[src]. D4 float4's per row.
// ---------------------------------------------------------------------------
template<int D4>
__global__ void scatter_kernel(const float* __restrict__ h,
                               const int*   __restrict__ ei,
                               float*       __restrict__ agg,
                               int n_edges) {
    int t    = blockIdx.x * blockDim.x + threadIdx.x;
    int e    = t / D4;
    int lane = t - e * D4;
    if (e >= n_edges) return;
    int s = __ldg(ei + e);
    int d = __ldg(ei + n_edges + e);
    float4 v = __ldg((const float4*)h + (size_t)s * D4 + lane);
    float4* ad = (float4*)agg + (size_t)d * D4 + lane;
    asm volatile("red.global.add.v4.f32 [%0], {%1,%2,%3,%4};"
                 :: "l"(ad), "f"(v.x), "f"(v.y), "f"(v.z), "f"(v.w) : "memory");
}

// ---------------------------------------------------------------------------
// Fused per-layer MLP, one thread per node, packed f32x2 math.
//   h = relu( relu( BN( agg @ w1 + b1 ) ) @ w2 + b2 )
//   hout[node] = h ; pool[batch[node], pool_off + j] += h[j]
// ---------------------------------------------------------------------------
template<int DIN>
__global__ __launch_bounds__(128) void mlp_kernel(
    const float* __restrict__ agg,
    const float* __restrict__ w1, const float* __restrict__ b1,
    const float* __restrict__ gg, const float* __restrict__ bt,
    const float* __restrict__ rm, const float* __restrict__ rv,
    const float* __restrict__ w2, const float* __restrict__ b2,
    float*       __restrict__ hout,
    const int*   __restrict__ batch,
    float*       __restrict__ pool, int pool_off, int n_nodes)
{
    __shared__ float ws[DIN * 64];   // holds w1, then recycled for w2 (64*64 <= DIN*64)

    int tid = threadIdx.x;
    for (int i = tid; i < DIN * 64; i += 128) ws[i] = w1[i];
    __syncthreads();

    int  node   = blockIdx.x * 128 + tid;
    bool active = node < n_nodes;
    int  nodec  = active ? node : (n_nodes - 1);

    // ---- GEMM1 (packed): acc2[j2] accumulates columns {2*j2, 2*j2+1} ----
    ull acc2[32];
#pragma unroll
    for (int j = 0; j < 32; j++) acc2[j] = 0ull;

    const float4* arow = (const float4*)(agg + (size_t)nodec * DIN);
#pragma unroll 2
    for (int k4 = 0; k4 < DIN / 4; k4++) {
        float4 hv = __ldg(arow + k4);
        float hvv[4] = {hv.x, hv.y, hv.z, hv.w};
#pragma unroll
        for (int kk = 0; kk < 4; kk++) {
            ull hk2 = pack2(hvv[kk], hvv[kk]);
            const ulonglong2* wrow = (const ulonglong2*)(ws + (k4 * 4 + kk) * 64);
#pragma unroll
            for (int j8 = 0; j8 < 16; j8++) {
                ulonglong2 wv = wrow[j8];
                acc2[j8 * 2 + 0] = fma2(hk2, wv.x, acc2[j8 * 2 + 0]);
                acc2[j8 * 2 + 1] = fma2(hk2, wv.y, acc2[j8 * 2 + 1]);
            }
        }
    }

    // ---- BN (eval, folded) + ReLU -> h kept packed in registers ----
    ull h2[32];
#pragma unroll
    for (int j2 = 0; j2 < 32; j2++) {
        float a, b;
        unpack2(acc2[j2], a, b);
        int j = j2 * 2;
        float sc0 = __ldg(gg + j)     * rsqrtf(__ldg(rv + j)     + 1e-5f);
        float sc1 = __ldg(gg + j + 1) * rsqrtf(__ldg(rv + j + 1) + 1e-5f);
        float sh0 = (__ldg(b1 + j)     - __ldg(rm + j))     * sc0 + __ldg(bt + j);
        float sh1 = (__ldg(b1 + j + 1) - __ldg(rm + j + 1)) * sc1 + __ldg(bt + j + 1);
        a = fmaxf(fmaf(a, sc0, sh0), 0.f);
        b = fmaxf(fmaf(b, sc1, sh1), 0.f);
        h2[j2] = pack2(a, b);
    }

    // ---- swap smem buffer to w2 ----
    __syncthreads();
    for (int i = tid; i < 64 * 64; i += 128) ws[i] = w2[i];
    __syncthreads();

    // ---- GEMM2 (packed) in two 32-column chunks, h read from registers ----
    float4* orow = (float4*)(hout + (size_t)node * 64);
    float*  prow = active ? (pool + (size_t)__ldg(batch + node) * 192 + pool_off) : pool;

#pragma unroll
    for (int jc = 0; jc < 2; jc++) {
        ull out2[16];
#pragma unroll
        for (int j = 0; j < 16; j++) out2[j] = 0ull;

#pragma unroll
        for (int k2 = 0; k2 < 32; k2++) {
            float hlo, hhi;
            unpack2(h2[k2], hlo, hhi);
            {
                ull hk2 = pack2(hlo, hlo);
                const ulonglong2* wrow = (const ulonglong2*)(ws + (k2 * 2) * 64 + jc * 32);
#pragma unroll
                for (int j8 = 0; j8 < 8; j8++) {
                    ulonglong2 wv = wrow[j8];
                    out2[j8 * 2 + 0] = fma2(hk2, wv.x, out2[j8 * 2 + 0]);
                    out2[j8 * 2 + 1] = fma2(hk2, wv.y, out2[j8 * 2 + 1]);
                }
            }
            {
                ull hk2 = pack2(hhi, hhi);
                const ulonglong2* wrow = (const ulonglong2*)(ws + (k2 * 2 + 1) * 64 + jc * 32);
#pragma unroll
                for (int j8 = 0; j8 < 8; j8++) {
                    ulonglong2 wv = wrow[j8];
                    out2[j8 * 2 + 0] = fma2(hk2, wv.x, out2[j8 * 2 + 0]);
                    out2[j8 * 2 + 1] = fma2(hk2, wv.y, out2[j8 * 2 + 1]);
                }
            }
        }

        // bias + ReLU + store + pooled reduction for this 32-col chunk
        if (active) {
#pragma unroll
            for (int q = 0; q < 8; q++) {
                int j = jc * 32 + q * 4;
                float a0, a1, a2, a3;
                unpack2(out2[q * 2 + 0], a0, a1);
                unpack2(out2[q * 2 + 1], a2, a3);
                float4 v;
                v.x = fmaxf(a0 + __ldg(b2 + j + 0), 0.f);
                v.y = fmaxf(a1 + __ldg(b2 + j + 1), 0.f);
                v.z = fmaxf(a2 + __ldg(b2 + j + 2), 0.f);
                v.w = fmaxf(a3 + __ldg(b2 + j + 3), 0.f);
                orow[jc * 8 + q] = v;
                asm volatile("red.global.add.v4.f32 [%0], {%1,%2,%3,%4};"
                             :: "l"(prow + j), "f"(v.x), "f"(v.y), "f"(v.z), "f"(v.w)
                             : "memory");
            }
        }
    }
}

// ---------------------------------------------------------------------------
__global__ void final_kernel(const float* __restrict__ pool,
                             const float* __restrict__ lw1, const float* __restrict__ lb1,
                             const float* __restrict__ lw2, const float* __restrict__ lb2,
                             float* __restrict__ out)
{
    __shared__ float prow[192];
    __shared__ float hid[64];
    __shared__ float zz[2];
    int g = blockIdx.x, j = threadIdx.x;
    for (int k = j; k < 192; k += 64) prow[k] = pool[g * 192 + k];
    __syncthreads();
    float a = __ldg(lb1 + j);
    for (int k = 0; k < 192; k++) a = fmaf(prow[k], __ldg(lw1 + k * 64 + j), a);
    hid[j] = fmaxf(a, 0.f);
    __syncthreads();
    if (j < 2) {
        float z = __ldg(lb2 + j);
#pragma unroll 8
        for (int k = 0; k < 64; k++) z = fmaf(hid[k], __ldg(lw2 + k * 2 + j), z);
        zz[j] = z;
    }
    __syncthreads();
    if (j == 0) {
        float m   = fmaxf(zz[0], zz[1]);
        float lse = m + logf(expf(zz[0] - m) + expf(zz[1] - m));
        out[g * 2 + 0] = zz[0] - lse;
        out[g * 2 + 1] = zz[1] - lse;
    }
}

// ---------------------------------------------------------------------------
extern "C" void kernel_launch(void* const* d_in, const int* in_sizes, int n_in,
                              void* d_out, int out_size)
{
    const float* x     = (const float*)d_in[0];
    const int*   ei    = (const int*)  d_in[1];
    const int*   batch = (const int*)  d_in[2];

    int wi = (in_sizes[3] < 64) ? 4 : 3;
    const float* W[28];
    for (int i = 0; i < 28 && wi + i < n_in; i++) W[i] = (const float*)d_in[wi + i];

    int n_nodes = in_sizes[0] / 128;
    int n_edges = in_sizes[1] / 2;

    float *agg, *h1, *h2, *h3, *pool;
    cudaGetSymbolAddress((void**)&agg,  g_agg);
    cudaGetSymbolAddress((void**)&h1,   g_h1);
    cudaGetSymbolAddress((void**)&h2,   g_h2);
    cudaGetSymbolAddress((void**)&h3,   g_h3);
    cudaGetSymbolAddress((void**)&pool, g_pool);

    float* out = (float*)d_out;

    zero_kernel<<<(NGRAPH * 192 + 255) / 256, 256>>>(pool, NGRAPH * 192);

    // ---- layer 1 (DIN = 128) ----
    {
        int n4 = n_nodes * 128 / 4;
        copy4_kernel<<<(n4 + 255) / 256, 256>>>((float4*)agg, (const float4*)x, n4);
        long long tt = (long long)n_edges * 32;
        scatter_kernel<32><<<(int)((tt + 255) / 256), 256>>>(x, ei, agg, n_edges);
        mlp_kernel<128><<<(n_nodes + 127) / 128, 128>>>(
            agg, W[0], W[1], W[2], W[3], W[4], W[5], W[6], W[7],
            h1, batch, pool, 0, n_nodes);
    }
    // ---- layer 2 (DIN = 64) ----
    {
        int n4 = n_nodes * 64 / 4;
        copy4_kernel<<<(n4 + 255) / 256, 256>>>((float4*)agg, (const float4*)h1, n4);
        long long tt = (long long)n_edges * 16;
        scatter_kernel<16><<<(int)((tt + 255) / 256), 256>>>(h1, ei, agg, n_edges);
        mlp_kernel<64><<<(n_nodes + 127) / 128, 128>>>(
            agg, W[8], W[9], W[10], W[11], W[12], W[13], W[14], W[15],
            h2, batch, pool, 64, n_nodes);
    }
    // ---- layer 3 (DIN = 64) ----
    {
        int n4 = n_nodes * 64 / 4;
        copy4_kernel<<<(n4 + 255) / 256, 256>>>((float4*)agg, (const float4*)h2, n4);
        long long tt = (long long)n_edges * 16;
        scatter_kernel<16><<<(int)((tt + 255) / 256), 256>>>(h2, ei, agg, n_edges);
        mlp_kernel<64><<<(n_nodes + 127) / 128, 128>>>(
            agg, W[16], W[17], W[18], W[19], W[20], W[21], W[22], W[23],
            h3, batch, pool, 128, n_nodes);
    }

    final_kernel<<<NGRAPH, 64>>>(pool, W[24], W[25], W[26], W[27], out);
}

// round 3
// speedup vs baseline: 1.4335x; 1.0296x over previous
#include <cuda_runtime.h>
#include <math.h>

// ---------------------------------------------------------------------------
// GIN (3 GINConv layers + BN + ReLU + MLP head)
//   N_NODES=100000, N_EDGES=1200000, D_IN=128, D_H=64, N_GRAPHS=256
// R2 changes vs R1:
//   * layer1 uses linearity: y = x@w1 FIRST (128->64), aggregate 64-dim y
//   * CSR built per launch (hist + scan + fill), pull-based aggregation
//     (registers, no fp atomics, no copy kernels)
// ---------------------------------------------------------------------------

#define MAX_NODES 100000
#define MAX_EDGES 1200000
#define NGRAPH    256

__device__ float g_buf [MAX_NODES * 128];     // y (first 64*N) | z (second 64*N)
__device__ float g_h1  [MAX_NODES * 64];
__device__ float g_h2  [MAX_NODES * 64];
__device__ float g_h3  [MAX_NODES * 64];
__device__ float g_pool[NGRAPH * 192];
__device__ int   g_deg [MAX_NODES + 1];
__device__ int   g_row [MAX_NODES + 1];
__device__ int   g_cur [MAX_NODES];
__device__ int   g_col [MAX_EDGES];

typedef unsigned long long ull;

__device__ __forceinline__ ull pack2(float lo, float hi) {
    ull r; asm("mov.b64 %0,{%1,%2};" : "=l"(r) : "f"(lo), "f"(hi)); return r;
}
__device__ __forceinline__ void unpack2(ull v, float& lo, float& hi) {
    asm("mov.b64 {%0,%1},%2;" : "=f"(lo), "=f"(hi) : "l"(v));
}
__device__ __forceinline__ ull fma2(ull a, ull b, ull c) {
    ull d; asm("fma.rn.f32x2 %0,%1,%2,%3;" : "=l"(d) : "l"(a), "l"(b), "l"(c)); return d;
}

// ---------------------------------------------------------------------------
__global__ void zero_f_kernel(float* __restrict__ p, int n) {
    int i = blockIdx.x * blockDim.x + threadIdx.x;
    if (i < n) p[i] = 0.f;
}
__global__ void zero_i_kernel(int* __restrict__ p, int n) {
    int i = blockIdx.x * blockDim.x + threadIdx.x;
    if (i < n) p[i] = 0;
}

// ---------------------------------------------------------------------------
// CSR build
// ---------------------------------------------------------------------------
__global__ void hist_kernel(const int* __restrict__ ei, int* __restrict__ deg, int n_edges) {
    int e = blockIdx.x * blockDim.x + threadIdx.x;
    if (e < n_edges) atomicAdd(deg + __ldg(ei + n_edges + e), 1);
}

__global__ void scan_kernel(const int* __restrict__ deg, int* __restrict__ rowptr,
                            int* __restrict__ cur, int n) {
    __shared__ int part[1024];
    int tid = threadIdx.x;
    int chunk = (n + 1023) / 1024;
    int beg = tid * chunk;
    int end = beg + chunk; if (end > n) end = n;
    int s = 0;
    for (int i = beg; i < end; i++) s += deg[i];
    part[tid] = s;
    __syncthreads();
    for (int off = 1; off < 1024; off *= 2) {
        int v = (tid >= off) ? part[tid - off] : 0;
        __syncthreads();
        part[tid] += v;
        __syncthreads();
    }
    int run = (tid == 0) ? 0 : part[tid - 1];
    for (int i = beg; i < end; i++) {
        rowptr[i] = run; cur[i] = run; run += deg[i];
    }
    if (tid == 0) rowptr[n] = part[1023];
}

__global__ void fill_kernel(const int* __restrict__ ei, int* __restrict__ cur,
                            int* __restrict__ col, int n_edges) {
    int e = blockIdx.x * blockDim.x + threadIdx.x;
    if (e >= n_edges) return;
    int s = __ldg(ei + e);
    int d = __ldg(ei + n_edges + e);
    int pos = atomicAdd(cur + d, 1);
    col[pos] = s;
}

// ---------------------------------------------------------------------------
// Pull aggregation on 64-dim rows: out[i] = in[i] + sum_{j in nb(i)} in[j]
// 16 threads per node, one float4 each; 4-way unrolled neighbor loop (MLP).
// ---------------------------------------------------------------------------
__global__ void pull64_kernel(const float* __restrict__ hin,
                              const int* __restrict__ rowptr,
                              const int* __restrict__ col,
                              float* __restrict__ hout, int n_nodes) {
    int t = blockIdx.x * blockDim.x + threadIdx.x;
    int node = t >> 4, lane = t & 15;
    if (node >= n_nodes) return;
    const float4* base = (const float4*)hin;
    float4 acc = __ldg(base + (size_t)node * 16 + lane);
    int e   = __ldg(rowptr + node);
    int end = __ldg(rowptr + node + 1);
    for (; e + 4 <= end; e += 4) {
        int s0 = __ldg(col + e), s1 = __ldg(col + e + 1);
        int s2 = __ldg(col + e + 2), s3 = __ldg(col + e + 3);
        float4 v0 = __ldg(base + (size_t)s0 * 16 + lane);
        float4 v1 = __ldg(base + (size_t)s1 * 16 + lane);
        float4 v2 = __ldg(base + (size_t)s2 * 16 + lane);
        float4 v3 = __ldg(base + (size_t)s3 * 16 + lane);
        acc.x += (v0.x + v1.x) + (v2.x + v3.x);
        acc.y += (v0.y + v1.y) + (v2.y + v3.y);
        acc.z += (v0.z + v1.z) + (v2.z + v3.z);
        acc.w += (v0.w + v1.w) + (v2.w + v3.w);
    }
    for (; e < end; e++) {
        int s = __ldg(col + e);
        float4 v = __ldg(base + (size_t)s * 16 + lane);
        acc.x += v.x; acc.y += v.y; acc.z += v.z; acc.w += v.w;
    }
    ((float4*)hout)[(size_t)node * 16 + lane] = acc;
}

// ---------------------------------------------------------------------------
// gemmA: y = x @ w1   (x: [N,128], w1: [128,64]) — no bias, packed f32x2.
// ---------------------------------------------------------------------------
__global__ __launch_bounds__(128) void gemmA_kernel(
    const float* __restrict__ x, const float* __restrict__ w1,
    float* __restrict__ y, int n_nodes)
{
    __shared__ float ws[128 * 64];
    int tid = threadIdx.x;
    for (int i = tid; i < 128 * 64; i += 128) ws[i] = w1[i];
    __syncthreads();

    int  node   = blockIdx.x * 128 + tid;
    bool active = node < n_nodes;
    int  nodec  = active ? node : (n_nodes - 1);

    ull acc2[32];
#pragma unroll
    for (int j = 0; j < 32; j++) acc2[j] = 0ull;

    const float4* arow = (const float4*)(x + (size_t)nodec * 128);
#pragma unroll 2
    for (int k4 = 0; k4 < 32; k4++) {
        float4 hv = __ldg(arow + k4);
        float hvv[4] = {hv.x, hv.y, hv.z, hv.w};
#pragma unroll
        for (int kk = 0; kk < 4; kk++) {
            ull hk2 = pack2(hvv[kk], hvv[kk]);
            const ulonglong2* wrow = (const ulonglong2*)(ws + (k4 * 4 + kk) * 64);
#pragma unroll
            for (int j8 = 0; j8 < 16; j8++) {
                ulonglong2 wv = wrow[j8];
                acc2[j8 * 2 + 0] = fma2(hk2, wv.x, acc2[j8 * 2 + 0]);
                acc2[j8 * 2 + 1] = fma2(hk2, wv.y, acc2[j8 * 2 + 1]);
            }
        }
    }

    if (active) {
        float4* orow = (float4*)(y + (size_t)node * 64);
#pragma unroll
        for (int q = 0; q < 16; q++) {
            float a, b, c, d;
            unpack2(acc2[q * 2 + 0], a, b);
            unpack2(acc2[q * 2 + 1], c, d);
            orow[q] = make_float4(a, b, c, d);
        }
    }
}

// ---------------------------------------------------------------------------
// mlpB: h = relu( relu(BN(z + b1)) @ w2 + b2 ); store + pool red.
// (z already contains (x+agg)@w1; BN shift folds in b1.)
// ---------------------------------------------------------------------------
__global__ __launch_bounds__(128) void mlpB_kernel(
    const float* __restrict__ z,
    const float* __restrict__ b1,
    const float* __restrict__ gg, const float* __restrict__ bt,
    const float* __restrict__ rm, const float* __restrict__ rv,
    const float* __restrict__ w2, const float* __restrict__ b2,
    float*       __restrict__ hout,
    const int*   __restrict__ batch,
    float*       __restrict__ pool, int pool_off, int n_nodes)
{
    __shared__ float ws[64 * 64];
    int tid = threadIdx.x;
    for (int i = tid; i < 64 * 64; i += 128) ws[i] = w2[i];
    __syncthreads();

    int  node   = blockIdx.x * 128 + tid;
    bool active = node < n_nodes;
    int  nodec  = active ? node : (n_nodes - 1);

    // load z row, BN + ReLU -> packed h2
    ull h2[32];
    const float4* zrow = (const float4*)(z + (size_t)nodec * 64);
#pragma unroll
    for (int q = 0; q < 16; q++) {
        float4 v = __ldg(zrow + q);
        int j = q * 4;
        float vv[4] = {v.x, v.y, v.z, v.w};
#pragma unroll
        for (int u = 0; u < 4; u += 2) {
            float sc0 = __ldg(gg + j + u)     * rsqrtf(__ldg(rv + j + u)     + 1e-5f);
            float sc1 = __ldg(gg + j + u + 1) * rsqrtf(__ldg(rv + j + u + 1) + 1e-5f);
            float sh0 = (__ldg(b1 + j + u)     - __ldg(rm + j + u))     * sc0 + __ldg(bt + j + u);
            float sh1 = (__ldg(b1 + j + u + 1) - __ldg(rm + j + u + 1)) * sc1 + __ldg(bt + j + u + 1);
            float a = fmaxf(fmaf(vv[u],     sc0, sh0), 0.f);
            float b = fmaxf(fmaf(vv[u + 1], sc1, sh1), 0.f);
            h2[q * 2 + u / 2] = pack2(a, b);
        }
    }

    float4* orow = (float4*)(hout + (size_t)node * 64);
    float*  prow = active ? (pool + (size_t)__ldg(batch + node) * 192 + pool_off) : pool;

#pragma unroll
    for (int jc = 0; jc < 2; jc++) {
        ull out2[16];
#pragma unroll
        for (int j = 0; j < 16; j++) out2[j] = 0ull;
#pragma unroll
        for (int k2 = 0; k2 < 32; k2++) {
            float hlo, hhi;
            unpack2(h2[k2], hlo, hhi);
            {
                ull hk2 = pack2(hlo, hlo);
                const ulonglong2* wrow = (const ulonglong2*)(ws + (k2 * 2) * 64 + jc * 32);
#pragma unroll
                for (int j8 = 0; j8 < 8; j8++) {
                    ulonglong2 wv = wrow[j8];
                    out2[j8 * 2 + 0] = fma2(hk2, wv.x, out2[j8 * 2 + 0]);
                    out2[j8 * 2 + 1] = fma2(hk2, wv.y, out2[j8 * 2 + 1]);
                }
            }
            {
                ull hk2 = pack2(hhi, hhi);
                const ulonglong2* wrow = (const ulonglong2*)(ws + (k2 * 2 + 1) * 64 + jc * 32);
#pragma unroll
                for (int j8 = 0; j8 < 8; j8++) {
                    ulonglong2 wv = wrow[j8];
                    out2[j8 * 2 + 0] = fma2(hk2, wv.x, out2[j8 * 2 + 0]);
                    out2[j8 * 2 + 1] = fma2(hk2, wv.y, out2[j8 * 2 + 1]);
                }
            }
        }
        if (active) {
#pragma unroll
            for (int q = 0; q < 8; q++) {
                int j = jc * 32 + q * 4;
                float a0, a1, a2, a3;
                unpack2(out2[q * 2 + 0], a0, a1);
                unpack2(out2[q * 2 + 1], a2, a3);
                float4 v;
                v.x = fmaxf(a0 + __ldg(b2 + j + 0), 0.f);
                v.y = fmaxf(a1 + __ldg(b2 + j + 1), 0.f);
                v.z = fmaxf(a2 + __ldg(b2 + j + 2), 0.f);
                v.w = fmaxf(a3 + __ldg(b2 + j + 3), 0.f);
                orow[jc * 8 + q] = v;
                asm volatile("red.global.add.v4.f32 [%0], {%1,%2,%3,%4};"
                             :: "l"(prow + j), "f"(v.x), "f"(v.y), "f"(v.z), "f"(v.w)
                             : "memory");
            }
        }
    }
}

// ---------------------------------------------------------------------------
// mlp64: full fused layer for layers 2/3: input agg z (64-dim).
//   h = relu( relu( BN( z @ w1 + b1 ) ) @ w2 + b2 ) ; store + pool red.
// ---------------------------------------------------------------------------
__global__ __launch_bounds__(128) void mlp64_kernel(
    const float* __restrict__ agg,
    const float* __restrict__ w1, const float* __restrict__ b1,
    const float* __restrict__ gg, const float* __restrict__ bt,
    const float* __restrict__ rm, const float* __restrict__ rv,
    const float* __restrict__ w2, const float* __restrict__ b2,
    float*       __restrict__ hout,
    const int*   __restrict__ batch,
    float*       __restrict__ pool, int pool_off, int n_nodes)
{
    __shared__ float ws[64 * 64];
    int tid = threadIdx.x;
    for (int i = tid; i < 64 * 64; i += 128) ws[i] = w1[i];
    __syncthreads();

    int  node   = blockIdx.x * 128 + tid;
    bool active = node < n_nodes;
    int  nodec  = active ? node : (n_nodes - 1);

    ull acc2[32];
#pragma unroll
    for (int j = 0; j < 32; j++) acc2[j] = 0ull;

    const float4* arow = (const float4*)(agg + (size_t)nodec * 64);
#pragma unroll 2
    for (int k4 = 0; k4 < 16; k4++) {
        float4 hv = __ldg(arow + k4);
        float hvv[4] = {hv.x, hv.y, hv.z, hv.w};
#pragma unroll
        for (int kk = 0; kk < 4; kk++) {
            ull hk2 = pack2(hvv[kk], hvv[kk]);
            const ulonglong2* wrow = (const ulonglong2*)(ws + (k4 * 4 + kk) * 64);
#pragma unroll
            for (int j8 = 0; j8 < 16; j8++) {
                ulonglong2 wv = wrow[j8];
                acc2[j8 * 2 + 0] = fma2(hk2, wv.x, acc2[j8 * 2 + 0]);
                acc2[j8 * 2 + 1] = fma2(hk2, wv.y, acc2[j8 * 2 + 1]);
            }
        }
    }

    ull h2[32];
#pragma unroll
    for (int j2 = 0; j2 < 32; j2++) {
        float a, b;
        unpack2(acc2[j2], a, b);
        int j = j2 * 2;
        float sc0 = __ldg(gg + j)     * rsqrtf(__ldg(rv + j)     + 1e-5f);
        float sc1 = __ldg(gg + j + 1) * rsqrtf(__ldg(rv + j + 1) + 1e-5f);
        float sh0 = (__ldg(b1 + j)     - __ldg(rm + j))     * sc0 + __ldg(bt + j);
        float sh1 = (__ldg(b1 + j + 1) - __ldg(rm + j + 1)) * sc1 + __ldg(bt + j + 1);
        a = fmaxf(fmaf(a, sc0, sh0), 0.f);
        b = fmaxf(fmaf(b, sc1, sh1), 0.f);
        h2[j2] = pack2(a, b);
    }

    __syncthreads();
    for (int i = tid; i < 64 * 64; i += 128) ws[i] = w2[i];
    __syncthreads();

    float4* orow = (float4*)(hout + (size_t)node * 64);
    float*  prow = active ? (pool + (size_t)__ldg(batch + node) * 192 + pool_off) : pool;

#pragma unroll
    for (int jc = 0; jc < 2; jc++) {
        ull out2[16];
#pragma unroll
        for (int j = 0; j < 16; j++) out2[j] = 0ull;
#pragma unroll
        for (int k2 = 0; k2 < 32; k2++) {
            float hlo, hhi;
            unpack2(h2[k2], hlo, hhi);
            {
                ull hk2 = pack2(hlo, hlo);
                const ulonglong2* wrow = (const ulonglong2*)(ws + (k2 * 2) * 64 + jc * 32);
#pragma unroll
                for (int j8 = 0; j8 < 8; j8++) {
                    ulonglong2 wv = wrow[j8];
                    out2[j8 * 2 + 0] = fma2(hk2, wv.x, out2[j8 * 2 + 0]);
                    out2[j8 * 2 + 1] = fma2(hk2, wv.y, out2[j8 * 2 + 1]);
                }
            }
            {
                ull hk2 = pack2(hhi, hhi);
                const ulonglong2* wrow = (const ulonglong2*)(ws + (k2 * 2 + 1) * 64 + jc * 32);
#pragma unroll
                for (int j8 = 0; j8 < 8; j8++) {
                    ulonglong2 wv = wrow[j8];
                    out2[j8 * 2 + 0] = fma2(hk2, wv.x, out2[j8 * 2 + 0]);
                    out2[j8 * 2 + 1] = fma2(hk2, wv.y, out2[j8 * 2 + 1]);
                }
            }
        }
        if (active) {
#pragma unroll
            for (int q = 0; q < 8; q++) {
                int j = jc * 32 + q * 4;
                float a0, a1, a2, a3;
                unpack2(out2[q * 2 + 0], a0, a1);
                unpack2(out2[q * 2 + 1], a2, a3);
                float4 v;
                v.x = fmaxf(a0 + __ldg(b2 + j + 0), 0.f);
                v.y = fmaxf(a1 + __ldg(b2 + j + 1), 0.f);
                v.z = fmaxf(a2 + __ldg(b2 + j + 2), 0.f);
                v.w = fmaxf(a3 + __ldg(b2 + j + 3), 0.f);
                orow[jc * 8 + q] = v;
                asm volatile("red.global.add.v4.f32 [%0], {%1,%2,%3,%4};"
                             :: "l"(prow + j), "f"(v.x), "f"(v.y), "f"(v.z), "f"(v.w)
                             : "memory");
            }
        }
    }
}

// ---------------------------------------------------------------------------
__global__ void final_kernel(const float* __restrict__ pool,
                             const float* __restrict__ lw1, const float* __restrict__ lb1,
                             const float* __restrict__ lw2, const float* __restrict__ lb2,
                             float* __restrict__ out)
{
    __shared__ float prow[192];
    __shared__ float hid[64];
    __shared__ float zz[2];
    int g = blockIdx.x, j = threadIdx.x;
    for (int k = j; k < 192; k += 64) prow[k] = pool[g * 192 + k];
    __syncthreads();
    float a = __ldg(lb1 + j);
    for (int k = 0; k < 192; k++) a = fmaf(prow[k], __ldg(lw1 + k * 64 + j), a);
    hid[j] = fmaxf(a, 0.f);
    __syncthreads();
    if (j < 2) {
        float z = __ldg(lb2 + j);
#pragma unroll 8
        for (int k = 0; k < 64; k++) z = fmaf(hid[k], __ldg(lw2 + k * 2 + j), z);
        zz[j] = z;
    }
    __syncthreads();
    if (j == 0) {
        float m   = fmaxf(zz[0], zz[1]);
        float lse = m + logf(expf(zz[0] - m) + expf(zz[1] - m));
        out[g * 2 + 0] = zz[0] - lse;
        out[g * 2 + 1] = zz[1] - lse;
    }
}

// ---------------------------------------------------------------------------
extern "C" void kernel_launch(void* const* d_in, const int* in_sizes, int n_in,
                              void* d_out, int out_size)
{
    const float* x     = (const float*)d_in[0];
    const int*   ei    = (const int*)  d_in[1];
    const int*   batch = (const int*)  d_in[2];

    int wi = (in_sizes[3] < 64) ? 4 : 3;
    const float* W[28];
    for (int i = 0; i < 28 && wi + i < n_in; i++) W[i] = (const float*)d_in[wi + i];

    int n_nodes = in_sizes[0] / 128;
    int n_edges = in_sizes[1] / 2;

    float *buf, *h1, *h2, *h3, *pool;
    int *deg, *row, *cur, *col;
    cudaGetSymbolAddress((void**)&buf,  g_buf);
    cudaGetSymbolAddress((void**)&h1,   g_h1);
    cudaGetSymbolAddress((void**)&h2,   g_h2);
    cudaGetSymbolAddress((void**)&h3,   g_h3);
    cudaGetSymbolAddress((void**)&pool, g_pool);
    cudaGetSymbolAddress((void**)&deg,  g_deg);
    cudaGetSymbolAddress((void**)&row,  g_row);
    cudaGetSymbolAddress((void**)&cur,  g_cur);
    cudaGetSymbolAddress((void**)&col,  g_col);

    float* y = buf;
    float* z = buf + (size_t)MAX_NODES * 64;
    float* out = (float*)d_out;

    int nodeBlocks = (n_nodes + 127) / 128;
    int pullBlocks = (n_nodes * 16 + 255) / 256;

    // ---- CSR build ----
    zero_i_kernel<<<(n_nodes + 1 + 255) / 256, 256>>>(deg, n_nodes + 1);
    zero_f_kernel<<<(NGRAPH * 192 + 255) / 256, 256>>>(pool, NGRAPH * 192);
    hist_kernel<<<(n_edges + 255) / 256, 256>>>(ei, deg, n_edges);
    scan_kernel<<<1, 1024>>>(deg, row, cur, n_nodes);
    fill_kernel<<<(n_edges + 255) / 256, 256>>>(ei, cur, col, n_edges);

    // ---- layer 1: y = x@w11 ; z = pull(y) ; h1 = mlpB(z) ----
    gemmA_kernel<<<nodeBlocks, 128>>>(x, W[0], y, n_nodes);
    pull64_kernel<<<pullBlocks, 256>>>(y, row, col, z, n_nodes);
    mlpB_kernel<<<nodeBlocks, 128>>>(z, W[1], W[2], W[3], W[4], W[5], W[6], W[7],
                                     h1, batch, pool, 0, n_nodes);

    // ---- layer 2 ----
    pull64_kernel<<<pullBlocks, 256>>>(h1, row, col, z, n_nodes);
    mlp64_kernel<<<nodeBlocks, 128>>>(z, W[8], W[9], W[10], W[11], W[12], W[13], W[14], W[15],
                                      h2, batch, pool, 64, n_nodes);

    // ---- layer 3 ----
    pull64_kernel<<<pullBlocks, 256>>>(h2, row, col, z, n_nodes);
    mlp64_kernel<<<nodeBlocks, 128>>>(z, W[16], W[17], W[18], W[19], W[20], W[21], W[22], W[23],
                                      h3, batch, pool, 128, n_nodes);

    final_kernel<<<NGRAPH, 64>>>(pool, W[24], W[25], W[26], W[27], out);
}

// round 4
// speedup vs baseline: 1.8408x; 1.2842x over previous
#include <cuda_runtime.h>
#include <math.h>

// ---------------------------------------------------------------------------
// GIN (3 GINConv layers + BN + ReLU + MLP head)
//   N_NODES=100000, N_EDGES=1200000, D_IN=128, D_H=64, N_GRAPHS=256
// R3 changes vs R2:
//   * single-block scan (155us!) replaced by 3-phase multi-block scan (~9us)
// ---------------------------------------------------------------------------

#define MAX_NODES 100000
#define MAX_EDGES 1200000
#define NGRAPH    256
#define SCAN_B    1024
#define MAX_SCAN_BLOCKS 128   // ceil(100000/1024)=98

__device__ float g_buf [MAX_NODES * 128];     // y | z
__device__ float g_h1  [MAX_NODES * 64];
__device__ float g_h2  [MAX_NODES * 64];
__device__ float g_h3  [MAX_NODES * 64];
__device__ float g_pool[NGRAPH * 192];
__device__ int   g_deg [MAX_NODES + 1];
__device__ int   g_row [MAX_NODES + 1];
__device__ int   g_cur [MAX_NODES];
__device__ int   g_col [MAX_EDGES];
__device__ int   g_bsum[MAX_SCAN_BLOCKS];

typedef unsigned long long ull;

__device__ __forceinline__ ull pack2(float lo, float hi) {
    ull r; asm("mov.b64 %0,{%1,%2};" : "=l"(r) : "f"(lo), "f"(hi)); return r;
}
__device__ __forceinline__ void unpack2(ull v, float& lo, float& hi) {
    asm("mov.b64 {%0,%1},%2;" : "=f"(lo), "=f"(hi) : "l"(v));
}
__device__ __forceinline__ ull fma2(ull a, ull b, ull c) {
    ull d; asm("fma.rn.f32x2 %0,%1,%2,%3;" : "=l"(d) : "l"(a), "l"(b), "l"(c)); return d;
}

// ---------------------------------------------------------------------------
__global__ void zero_f_kernel(float* __restrict__ p, int n) {
    int i = blockIdx.x * blockDim.x + threadIdx.x;
    if (i < n) p[i] = 0.f;
}
__global__ void zero_i_kernel(int* __restrict__ p, int n) {
    int i = blockIdx.x * blockDim.x + threadIdx.x;
    if (i < n) p[i] = 0;
}

// ---------------------------------------------------------------------------
// CSR build
// ---------------------------------------------------------------------------
__global__ void hist_kernel(const int* __restrict__ ei, int* __restrict__ deg, int n_edges) {
    int e = blockIdx.x * blockDim.x + threadIdx.x;
    if (e < n_edges) atomicAdd(deg + __ldg(ei + n_edges + e), 1);
}

// phase 1: per-block reduction of deg
__global__ void bsum_kernel(const int* __restrict__ deg, int* __restrict__ bsum, int n) {
    __shared__ int sm[SCAN_B];
    int i = blockIdx.x * SCAN_B + threadIdx.x;
    sm[threadIdx.x] = (i < n) ? deg[i] : 0;
    __syncthreads();
#pragma unroll
    for (int off = SCAN_B / 2; off > 0; off >>= 1) {
        if (threadIdx.x < off) sm[threadIdx.x] += sm[threadIdx.x + off];
        __syncthreads();
    }
    if (threadIdx.x == 0) bsum[blockIdx.x] = sm[0];
}

// phase 2: exclusive scan of block sums (nb <= 128, trivial serial)
__global__ void bscan_kernel(int* __restrict__ bsum, int nb) {
    if (threadIdx.x == 0) {
        int run = 0;
        for (int i = 0; i < nb; i++) { int v = bsum[i]; bsum[i] = run; run += v; }
    }
}

// phase 3: per-block Hillis-Steele scan + block offset -> rowptr, cur
__global__ void scatter_scan_kernel(const int* __restrict__ deg,
                                    const int* __restrict__ bsum,
                                    int* __restrict__ rowptr, int* __restrict__ cur, int n) {
    __shared__ int sm[SCAN_B];
    int i = blockIdx.x * SCAN_B + threadIdx.x;
    int v = (i < n) ? deg[i] : 0;
    sm[threadIdx.x] = v;
    __syncthreads();
#pragma unroll
    for (int off = 1; off < SCAN_B; off *= 2) {
        int t = (threadIdx.x >= off) ? sm[threadIdx.x - off] : 0;
        __syncthreads();
        sm[threadIdx.x] += t;
        __syncthreads();
    }
    int excl = sm[threadIdx.x] - v + bsum[blockIdx.x];
    if (i < n) { rowptr[i] = excl; cur[i] = excl; }
    if (i == n - 1) rowptr[n] = excl + v;
}

__global__ void fill_kernel(const int* __restrict__ ei, int* __restrict__ cur,
                            int* __restrict__ col, int n_edges) {
    int e = blockIdx.x * blockDim.x + threadIdx.x;
    if (e >= n_edges) return;
    int s = __ldg(ei + e);
    int d = __ldg(ei + n_edges + e);
    int pos = atomicAdd(cur + d, 1);
    col[pos] = s;
}

// ---------------------------------------------------------------------------
// Pull aggregation on 64-dim rows: out[i] = in[i] + sum_{j in nb(i)} in[j]
// ---------------------------------------------------------------------------
__global__ void pull64_kernel(const float* __restrict__ hin,
                              const int* __restrict__ rowptr,
                              const int* __restrict__ col,
                              float* __restrict__ hout, int n_nodes) {
    int t = blockIdx.x * blockDim.x + threadIdx.x;
    int node = t >> 4, lane = t & 15;
    if (node >= n_nodes) return;
    const float4* base = (const float4*)hin;
    float4 acc = __ldg(base + (size_t)node * 16 + lane);
    int e   = __ldg(rowptr + node);
    int end = __ldg(rowptr + node + 1);
    for (; e + 4 <= end; e += 4) {
        int s0 = __ldg(col + e), s1 = __ldg(col + e + 1);
        int s2 = __ldg(col + e + 2), s3 = __ldg(col + e + 3);
        float4 v0 = __ldg(base + (size_t)s0 * 16 + lane);
        float4 v1 = __ldg(base + (size_t)s1 * 16 + lane);
        float4 v2 = __ldg(base + (size_t)s2 * 16 + lane);
        float4 v3 = __ldg(base + (size_t)s3 * 16 + lane);
        acc.x += (v0.x + v1.x) + (v2.x + v3.x);
        acc.y += (v0.y + v1.y) + (v2.y + v3.y);
        acc.z += (v0.z + v1.z) + (v2.z + v3.z);
        acc.w += (v0.w + v1.w) + (v2.w + v3.w);
    }
    for (; e < end; e++) {
        int s = __ldg(col + e);
        float4 v = __ldg(base + (size_t)s * 16 + lane);
        acc.x += v.x; acc.y += v.y; acc.z += v.z; acc.w += v.w;
    }
    ((float4*)hout)[(size_t)node * 16 + lane] = acc;
}

// ---------------------------------------------------------------------------
// gemmA: y = x @ w1   (x: [N,128], w1: [128,64]) — packed f32x2.
// ---------------------------------------------------------------------------
__global__ __launch_bounds__(128) void gemmA_kernel(
    const float* __restrict__ x, const float* __restrict__ w1,
    float* __restrict__ y, int n_nodes)
{
    __shared__ float ws[128 * 64];
    int tid = threadIdx.x;
    for (int i = tid; i < 128 * 64; i += 128) ws[i] = w1[i];
    __syncthreads();

    int  node   = blockIdx.x * 128 + tid;
    bool active = node < n_nodes;
    int  nodec  = active ? node : (n_nodes - 1);

    ull acc2[32];
#pragma unroll
    for (int j = 0; j < 32; j++) acc2[j] = 0ull;

    const float4* arow = (const float4*)(x + (size_t)nodec * 128);
#pragma unroll 2
    for (int k4 = 0; k4 < 32; k4++) {
        float4 hv = __ldg(arow + k4);
        float hvv[4] = {hv.x, hv.y, hv.z, hv.w};
#pragma unroll
        for (int kk = 0; kk < 4; kk++) {
            ull hk2 = pack2(hvv[kk], hvv[kk]);
            const ulonglong2* wrow = (const ulonglong2*)(ws + (k4 * 4 + kk) * 64);
#pragma unroll
            for (int j8 = 0; j8 < 16; j8++) {
                ulonglong2 wv = wrow[j8];
                acc2[j8 * 2 + 0] = fma2(hk2, wv.x, acc2[j8 * 2 + 0]);
                acc2[j8 * 2 + 1] = fma2(hk2, wv.y, acc2[j8 * 2 + 1]);
            }
        }
    }

    if (active) {
        float4* orow = (float4*)(y + (size_t)node * 64);
#pragma unroll
        for (int q = 0; q < 16; q++) {
            float a, b, c, d;
            unpack2(acc2[q * 2 + 0], a, b);
            unpack2(acc2[q * 2 + 1], c, d);
            orow[q] = make_float4(a, b, c, d);
        }
    }
}

// ---------------------------------------------------------------------------
// mlpB: h = relu( relu(BN(z + b1)) @ w2 + b2 ); store + pool red.
// ---------------------------------------------------------------------------
__global__ __launch_bounds__(128) void mlpB_kernel(
    const float* __restrict__ z,
    const float* __restrict__ b1,
    const float* __restrict__ gg, const float* __restrict__ bt,
    const float* __restrict__ rm, const float* __restrict__ rv,
    const float* __restrict__ w2, const float* __restrict__ b2,
    float*       __restrict__ hout,
    const int*   __restrict__ batch,
    float*       __restrict__ pool, int pool_off, int n_nodes)
{
    __shared__ float ws[64 * 64];
    int tid = threadIdx.x;
    for (int i = tid; i < 64 * 64; i += 128) ws[i] = w2[i];
    __syncthreads();

    int  node   = blockIdx.x * 128 + tid;
    bool active = node < n_nodes;
    int  nodec  = active ? node : (n_nodes - 1);

    ull h2[32];
    const float4* zrow = (const float4*)(z + (size_t)nodec * 64);
#pragma unroll
    for (int q = 0; q < 16; q++) {
        float4 v = __ldg(zrow + q);
        int j = q * 4;
        float vv[4] = {v.x, v.y, v.z, v.w};
#pragma unroll
        for (int u = 0; u < 4; u += 2) {
            float sc0 = __ldg(gg + j + u)     * rsqrtf(__ldg(rv + j + u)     + 1e-5f);
            float sc1 = __ldg(gg + j + u + 1) * rsqrtf(__ldg(rv + j + u + 1) + 1e-5f);
            float sh0 = (__ldg(b1 + j + u)     - __ldg(rm + j + u))     * sc0 + __ldg(bt + j + u);
            float sh1 = (__ldg(b1 + j + u + 1) - __ldg(rm + j + u + 1)) * sc1 + __ldg(bt + j + u + 1);
            float a = fmaxf(fmaf(vv[u],     sc0, sh0), 0.f);
            float b = fmaxf(fmaf(vv[u + 1], sc1, sh1), 0.f);
            h2[q * 2 + u / 2] = pack2(a, b);
        }
    }

    float4* orow = (float4*)(hout + (size_t)node * 64);
    float*  prow = active ? (pool + (size_t)__ldg(batch + node) * 192 + pool_off) : pool;

#pragma unroll
    for (int jc = 0; jc < 2; jc++) {
        ull out2[16];
#pragma unroll
        for (int j = 0; j < 16; j++) out2[j] = 0ull;
#pragma unroll
        for (int k2 = 0; k2 < 32; k2++) {
            float hlo, hhi;
            unpack2(h2[k2], hlo, hhi);
            {
                ull hk2 = pack2(hlo, hlo);
                const ulonglong2* wrow = (const ulonglong2*)(ws + (k2 * 2) * 64 + jc * 32);
#pragma unroll
                for (int j8 = 0; j8 < 8; j8++) {
                    ulonglong2 wv = wrow[j8];
                    out2[j8 * 2 + 0] = fma2(hk2, wv.x, out2[j8 * 2 + 0]);
                    out2[j8 * 2 + 1] = fma2(hk2, wv.y, out2[j8 * 2 + 1]);
                }
            }
            {
                ull hk2 = pack2(hhi, hhi);
                const ulonglong2* wrow = (const ulonglong2*)(ws + (k2 * 2 + 1) * 64 + jc * 32);
#pragma unroll
                for (int j8 = 0; j8 < 8; j8++) {
                    ulonglong2 wv = wrow[j8];
                    out2[j8 * 2 + 0] = fma2(hk2, wv.x, out2[j8 * 2 + 0]);
                    out2[j8 * 2 + 1] = fma2(hk2, wv.y, out2[j8 * 2 + 1]);
                }
            }
        }
        if (active) {
#pragma unroll
            for (int q = 0; q < 8; q++) {
                int j = jc * 32 + q * 4;
                float a0, a1, a2, a3;
                unpack2(out2[q * 2 + 0], a0, a1);
                unpack2(out2[q * 2 + 1], a2, a3);
                float4 v;
                v.x = fmaxf(a0 + __ldg(b2 + j + 0), 0.f);
                v.y = fmaxf(a1 + __ldg(b2 + j + 1), 0.f);
                v.z = fmaxf(a2 + __ldg(b2 + j + 2), 0.f);
                v.w = fmaxf(a3 + __ldg(b2 + j + 3), 0.f);
                orow[jc * 8 + q] = v;
                asm volatile("red.global.add.v4.f32 [%0], {%1,%2,%3,%4};"
                             :: "l"(prow + j), "f"(v.x), "f"(v.y), "f"(v.z), "f"(v.w)
                             : "memory");
            }
        }
    }
}

// ---------------------------------------------------------------------------
// mlp64: fused layer for layers 2/3
// ---------------------------------------------------------------------------
__global__ __launch_bounds__(128) void mlp64_kernel(
    const float* __restrict__ agg,
    const float* __restrict__ w1, const float* __restrict__ b1,
    const float* __restrict__ gg, const float* __restrict__ bt,
    const float* __restrict__ rm, const float* __restrict__ rv,
    const float* __restrict__ w2, const float* __restrict__ b2,
    float*       __restrict__ hout,
    const int*   __restrict__ batch,
    float*       __restrict__ pool, int pool_off, int n_nodes)
{
    __shared__ float ws[64 * 64];
    int tid = threadIdx.x;
    for (int i = tid; i < 64 * 64; i += 128) ws[i] = w1[i];
    __syncthreads();

    int  node   = blockIdx.x * 128 + tid;
    bool active = node < n_nodes;
    int  nodec  = active ? node : (n_nodes - 1);

    ull acc2[32];
#pragma unroll
    for (int j = 0; j < 32; j++) acc2[j] = 0ull;

    const float4* arow = (const float4*)(agg + (size_t)nodec * 64);
#pragma unroll 2
    for (int k4 = 0; k4 < 16; k4++) {
        float4 hv = __ldg(arow + k4);
        float hvv[4] = {hv.x, hv.y, hv.z, hv.w};
#pragma unroll
        for (int kk = 0; kk < 4; kk++) {
            ull hk2 = pack2(hvv[kk], hvv[kk]);
            const ulonglong2* wrow = (const ulonglong2*)(ws + (k4 * 4 + kk) * 64);
#pragma unroll
            for (int j8 = 0; j8 < 16; j8++) {
                ulonglong2 wv = wrow[j8];
                acc2[j8 * 2 + 0] = fma2(hk2, wv.x, acc2[j8 * 2 + 0]);
                acc2[j8 * 2 + 1] = fma2(hk2, wv.y, acc2[j8 * 2 + 1]);
            }
        }
    }

    ull h2[32];
#pragma unroll
    for (int j2 = 0; j2 < 32; j2++) {
        float a, b;
        unpack2(acc2[j2], a, b);
        int j = j2 * 2;
        float sc0 = __ldg(gg + j)     * rsqrtf(__ldg(rv + j)     + 1e-5f);
        float sc1 = __ldg(gg + j + 1) * rsqrtf(__ldg(rv + j + 1) + 1e-5f);
        float sh0 = (__ldg(b1 + j)     - __ldg(rm + j))     * sc0 + __ldg(bt + j);
        float sh1 = (__ldg(b1 + j + 1) - __ldg(rm + j + 1)) * sc1 + __ldg(bt + j + 1);
        a = fmaxf(fmaf(a, sc0, sh0), 0.f);
        b = fmaxf(fmaf(b, sc1, sh1), 0.f);
        h2[j2] = pack2(a, b);
    }

    __syncthreads();
    for (int i = tid; i < 64 * 64; i += 128) ws[i] = w2[i];
    __syncthreads();

    float4* orow = (float4*)(hout + (size_t)node * 64);
    float*  prow = active ? (pool + (size_t)__ldg(batch + node) * 192 + pool_off) : pool;

#pragma unroll
    for (int jc = 0; jc < 2; jc++) {
        ull out2[16];
#pragma unroll
        for (int j = 0; j < 16; j++) out2[j] = 0ull;
#pragma unroll
        for (int k2 = 0; k2 < 32; k2++) {
            float hlo, hhi;
            unpack2(h2[k2], hlo, hhi);
            {
                ull hk2 = pack2(hlo, hlo);
                const ulonglong2* wrow = (const ulonglong2*)(ws + (k2 * 2) * 64 + jc * 32);
#pragma unroll
                for (int j8 = 0; j8 < 8; j8++) {
                    ulonglong2 wv = wrow[j8];
                    out2[j8 * 2 + 0] = fma2(hk2, wv.x, out2[j8 * 2 + 0]);
                    out2[j8 * 2 + 1] = fma2(hk2, wv.y, out2[j8 * 2 + 1]);
                }
            }
            {
                ull hk2 = pack2(hhi, hhi);
                const ulonglong2* wrow = (const ulonglong2*)(ws + (k2 * 2 + 1) * 64 + jc * 32);
#pragma unroll
                for (int j8 = 0; j8 < 8; j8++) {
                    ulonglong2 wv = wrow[j8];
                    out2[j8 * 2 + 0] = fma2(hk2, wv.x, out2[j8 * 2 + 0]);
                    out2[j8 * 2 + 1] = fma2(hk2, wv.y, out2[j8 * 2 + 1]);
                }
            }
        }
        if (active) {
#pragma unroll
            for (int q = 0; q < 8; q++) {
                int j = jc * 32 + q * 4;
                float a0, a1, a2, a3;
                unpack2(out2[q * 2 + 0], a0, a1);
                unpack2(out2[q * 2 + 1], a2, a3);
                float4 v;
                v.x = fmaxf(a0 + __ldg(b2 + j + 0), 0.f);
                v.y = fmaxf(a1 + __ldg(b2 + j + 1), 0.f);
                v.z = fmaxf(a2 + __ldg(b2 + j + 2), 0.f);
                v.w = fmaxf(a3 + __ldg(b2 + j + 3), 0.f);
                orow[jc * 8 + q] = v;
                asm volatile("red.global.add.v4.f32 [%0], {%1,%2,%3,%4};"
                             :: "l"(prow + j), "f"(v.x), "f"(v.y), "f"(v.z), "f"(v.w)
                             : "memory");
            }
        }
    }
}

// ---------------------------------------------------------------------------
__global__ void final_kernel(const float* __restrict__ pool,
                             const float* __restrict__ lw1, const float* __restrict__ lb1,
                             const float* __restrict__ lw2, const float* __restrict__ lb2,
                             float* __restrict__ out)
{
    __shared__ float prow[192];
    __shared__ float hid[64];
    __shared__ float zz[2];
    int g = blockIdx.x, j = threadIdx.x;
    for (int k = j; k < 192; k += 64) prow[k] = pool[g * 192 + k];
    __syncthreads();
    float a = __ldg(lb1 + j);
    for (int k = 0; k < 192; k++) a = fmaf(prow[k], __ldg(lw1 + k * 64 + j), a);
    hid[j] = fmaxf(a, 0.f);
    __syncthreads();
    if (j < 2) {
        float z = __ldg(lb2 + j);
#pragma unroll 8
        for (int k = 0; k < 64; k++) z = fmaf(hid[k], __ldg(lw2 + k * 2 + j), z);
        zz[j] = z;
    }
    __syncthreads();
    if (j == 0) {
        float m   = fmaxf(zz[0], zz[1]);
        float lse = m + logf(expf(zz[0] - m) + expf(zz[1] - m));
        out[g * 2 + 0] = zz[0] - lse;
        out[g * 2 + 1] = zz[1] - lse;
    }
}

// ---------------------------------------------------------------------------
extern "C" void kernel_launch(void* const* d_in, const int* in_sizes, int n_in,
                              void* d_out, int out_size)
{
    const float* x     = (const float*)d_in[0];
    const int*   ei    = (const int*)  d_in[1];
    const int*   batch = (const int*)  d_in[2];

    int wi = (in_sizes[3] < 64) ? 4 : 3;
    const float* W[28];
    for (int i = 0; i < 28 && wi + i < n_in; i++) W[i] = (const float*)d_in[wi + i];

    int n_nodes = in_sizes[0] / 128;
    int n_edges = in_sizes[1] / 2;

    float *buf, *h1, *h2, *h3, *pool;
    int *deg, *row, *cur, *col, *bsum;
    cudaGetSymbolAddress((void**)&buf,  g_buf);
    cudaGetSymbolAddress((void**)&h1,   g_h1);
    cudaGetSymbolAddress((void**)&h2,   g_h2);
    cudaGetSymbolAddress((void**)&h3,   g_h3);
    cudaGetSymbolAddress((void**)&pool, g_pool);
    cudaGetSymbolAddress((void**)&deg,  g_deg);
    cudaGetSymbolAddress((void**)&row,  g_row);
    cudaGetSymbolAddress((void**)&cur,  g_cur);
    cudaGetSymbolAddress((void**)&col,  g_col);
    cudaGetSymbolAddress((void**)&bsum, g_bsum);

    float* y = buf;
    float* z = buf + (size_t)MAX_NODES * 64;
    float* out = (float*)d_out;

    int nodeBlocks = (n_nodes + 127) / 128;
    int pullBlocks = (n_nodes * 16 + 255) / 256;
    int scanBlocks = (n_nodes + SCAN_B - 1) / SCAN_B;

    // ---- CSR build (multi-block scan) ----
    zero_i_kernel<<<(n_nodes + 1 + 255) / 256, 256>>>(deg, n_nodes + 1);
    zero_f_kernel<<<(NGRAPH * 192 + 255) / 256, 256>>>(pool, NGRAPH * 192);
    hist_kernel<<<(n_edges + 255) / 256, 256>>>(ei, deg, n_edges);
    bsum_kernel<<<scanBlocks, SCAN_B>>>(deg, bsum, n_nodes);
    bscan_kernel<<<1, 32>>>(bsum, scanBlocks);
    scatter_scan_kernel<<<scanBlocks, SCAN_B>>>(deg, bsum, row, cur, n_nodes);
    fill_kernel<<<(n_edges + 255) / 256, 256>>>(ei, cur, col, n_edges);

    // ---- layer 1: y = x@w11 ; z = pull(y) ; h1 = mlpB(z) ----
    gemmA_kernel<<<nodeBlocks, 128>>>(x, W[0], y, n_nodes);
    pull64_kernel<<<pullBlocks, 256>>>(y, row, col, z, n_nodes);
    mlpB_kernel<<<nodeBlocks, 128>>>(z, W[1], W[2], W[3], W[4], W[5], W[6], W[7],
                                     h1, batch, pool, 0, n_nodes);

    // ---- layer 2 ----
    pull64_kernel<<<pullBlocks, 256>>>(h1, row, col, z, n_nodes);
    mlp64_kernel<<<nodeBlocks, 128>>>(z, W[8], W[9], W[10], W[11], W[12], W[13], W[14], W[15],
                                      h2, batch, pool, 64, n_nodes);

    // ---- layer 3 ----
    pull64_kernel<<<pullBlocks, 256>>>(h2, row, col, z, n_nodes);
    mlp64_kernel<<<nodeBlocks, 128>>>(z, W[16], W[17], W[18], W[19], W[20], W[21], W[22], W[23],
                                      h3, batch, pool, 128, n_nodes);

    final_kernel<<<NGRAPH, 64>>>(pool, W[24], W[25], W[26], W[27], out);
}